// round 16
// baseline (speedup 1.0000x reference)
#include <cuda_runtime.h>
#include <cuda_fp16.h>
#include <cstdint>
#include <math.h>

#define NN 50000
#define EE 800000
#define ET (NN + EE)          // 850000 edges incl. self loops

// ---------------- scratch (device globals; no allocation allowed) ----------
__device__ __half  g_xh[(size_t)NN * 128];   // x in fp16
__device__ __half  g_w1h[128 * 256];         // W1 fp16
__device__ __half  g_w2h[256 * 64];          // W2 fp16
__device__ __half  g_dw1h[64 * 64];          // dW1 fp16
__device__ __half  g_dw2h[64 * 128];         // dW2 fp16
__device__ __half  g_ax[(size_t)NN * 512];   // per-head aggregated x [node][h*128+c]
__device__ __half2 g_hh [(size_t)NN * 128];  // elu(gat1) fp16 (input to GEMM2)
__device__ __half2 g_h2h[(size_t)NN * 32];   // h2 fp16
__device__ __half2 g_zh [(size_t)NN * 32];   // z fp16 (decoder input)
__device__ __half2 g_th [(size_t)NN * 32];   // decoder hidden fp16
__device__ float g_vs[128 * 4];              // W1 @ att_src  [c][h]
__device__ float g_vd[128 * 4];              // W1 @ att_dst  [c][h]
__device__ float g_as1[NN * 4];
__device__ float g_ad1[NN * 4];
__device__ float g_as2[NN];
__device__ float g_ad2[NN];
__device__ int   g_deg[NN];
__device__ int   g_off[NN + 1];
__device__ int   g_cur[NN];
__device__ int   g_srcid[ET];
__device__ int   g_ei64;

__device__ __forceinline__ float lrelu(float v) { return v >= 0.f ? v : 0.2f * v; }

__device__ __forceinline__ int load_edge(const int* __restrict__ ei, int j) {
    return g_ei64 ? ei[(size_t)j * 2] : ei[j];   // little-endian low word
}

__global__ void k_flag(float* __restrict__ z, float v) { z[0] = v; }

__global__ void k_zero_out(float* __restrict__ o, int n) {
    int i = blockIdx.x * blockDim.x + threadIdx.x;
    if (i < n) o[i] = 0.f;
}

// ------- init: zero degrees + dtype detect ----------------------------------
__global__ void k_init(const int* __restrict__ ei) {
    int i = blockIdx.x * blockDim.x + threadIdx.x;
    if (i < NN) g_deg[i] = 0;
    if (i == 0) {
        int odd_nz = 0, even_nz = 0;
        for (int j = 0; j < 256; j += 2) {
            if (ei[j]     != 0) even_nz++;
            if (ei[j + 1] != 0) odd_nz++;
        }
        g_ei64 = (odd_nz == 0 && even_nz > 0) ? 1 : 0;
    }
}

// ------- fp32 -> fp16 conversion of x, W1, W2, dW1, dW2 (pairwise) ----------
#define XPAIRS 3200000
#define W1PAIRS 16384
#define W2PAIRS 8192
#define DW1PAIRS 2048
#define DW2PAIRS 4096
#define CVT_TOTAL (XPAIRS + W1PAIRS + W2PAIRS + DW1PAIRS + DW2PAIRS)
__global__ void k_cvt(const float* __restrict__ x, const float* __restrict__ W1,
                      const float* __restrict__ W2, const float* __restrict__ dW1,
                      const float* __restrict__ dW2) {
    int p = blockIdx.x * blockDim.x + threadIdx.x;
    if (p < XPAIRS) {
        float2 v = *(const float2*)&x[(size_t)p * 2];
        *(__half2*)&g_xh[(size_t)p * 2] = __floats2half2_rn(v.x, v.y);
    } else if (p < XPAIRS + W1PAIRS) {
        int q = p - XPAIRS;
        float2 v = *(const float2*)&W1[(size_t)q * 2];
        *(__half2*)&g_w1h[(size_t)q * 2] = __floats2half2_rn(v.x, v.y);
    } else if (p < XPAIRS + W1PAIRS + W2PAIRS) {
        int q = p - XPAIRS - W1PAIRS;
        float2 v = *(const float2*)&W2[(size_t)q * 2];
        *(__half2*)&g_w2h[(size_t)q * 2] = __floats2half2_rn(v.x, v.y);
    } else if (p < XPAIRS + W1PAIRS + W2PAIRS + DW1PAIRS) {
        int q = p - XPAIRS - W1PAIRS - W2PAIRS;
        float2 v = *(const float2*)&dW1[(size_t)q * 2];
        *(__half2*)&g_dw1h[(size_t)q * 2] = __floats2half2_rn(v.x, v.y);
    } else if (p < CVT_TOTAL) {
        int q = p - XPAIRS - W1PAIRS - W2PAIRS - DW1PAIRS;
        float2 v = *(const float2*)&dW2[(size_t)q * 2];
        *(__half2*)&g_dw2h[(size_t)q * 2] = __floats2half2_rn(v.x, v.y);
    }
}

// ------- v = W1 @ att  (fp32, tiny) -----------------------------------------
__global__ void k_v(const float* __restrict__ W1, const float* __restrict__ atts,
                    const float* __restrict__ attd) {
    int t = threadIdx.x;                 // 512 threads
    int c = t & 127, h = t >> 7;
    float ss = 0.f, sd = 0.f;
    #pragma unroll 8
    for (int j = 0; j < 64; j++) {
        float w = W1[c * 256 + h * 64 + j];
        ss += w * atts[h * 64 + j];
        sd += w * attd[h * 64 + j];
    }
    g_vs[c * 4 + h] = ss;
    g_vd[c * 4 + h] = sd;
}

// ------- a_s1/a_d1 = x @ v  (warp per node) ---------------------------------
__global__ void k_attx() {
    int node = (blockIdx.x * blockDim.x + threadIdx.x) >> 5;
    int lane = threadIdx.x & 31;
    if (node >= NN) return;
    int c0 = lane * 4;
    uint2 v = *(const uint2*)&g_xh[(size_t)node * 128 + c0];
    float2 f0 = __half22float2(*(__half2*)&v.x);
    float2 f1 = __half22float2(*(__half2*)&v.y);
    float xk[4] = {f0.x, f0.y, f1.x, f1.y};
    float ps[4] = {0.f, 0.f, 0.f, 0.f};
    float pd[4] = {0.f, 0.f, 0.f, 0.f};
    #pragma unroll
    for (int kk = 0; kk < 4; kk++) {
        float4 vs = *(const float4*)&g_vs[(c0 + kk) * 4];
        float4 vd = *(const float4*)&g_vd[(c0 + kk) * 4];
        ps[0] += xk[kk] * vs.x; ps[1] += xk[kk] * vs.y;
        ps[2] += xk[kk] * vs.z; ps[3] += xk[kk] * vs.w;
        pd[0] += xk[kk] * vd.x; pd[1] += xk[kk] * vd.y;
        pd[2] += xk[kk] * vd.z; pd[3] += xk[kk] * vd.w;
    }
    #pragma unroll
    for (int o = 16; o > 0; o >>= 1) {
        #pragma unroll
        for (int h = 0; h < 4; h++) {
            ps[h] += __shfl_xor_sync(0xffffffffu, ps[h], o);
            pd[h] += __shfl_xor_sync(0xffffffffu, pd[h], o);
        }
    }
    if (lane == 0) {
        *(float4*)&g_as1[node * 4] = make_float4(ps[0], ps[1], ps[2], ps[3]);
        *(float4*)&g_ad1[node * 4] = make_float4(pd[0], pd[1], pd[2], pd[3]);
    }
}

// ---------------- CSR build -------------------------------------------------
__global__ void k_count(const int* __restrict__ ei) {
    int e = blockIdx.x * blockDim.x + threadIdx.x;
    if (e >= ET) return;
    int dst = (e < EE) ? load_edge(ei, EE + e) : (e - EE);
    if ((unsigned)dst < (unsigned)NN) atomicAdd(&g_deg[dst], 1);
}

__global__ void k_scan1() {
    const int PER = 49;
    __shared__ int ws[32];
    int tid = threadIdx.x;
    int base = tid * PER;
    int sum = 0;
    for (int j = 0; j < PER; j++) { int idx = base + j; if (idx < NN) sum += g_deg[idx]; }
    int lane = tid & 31, w = tid >> 5;
    int v = sum;
    #pragma unroll
    for (int o = 1; o < 32; o <<= 1) {
        int t = __shfl_up_sync(0xffffffffu, v, o);
        if (lane >= o) v += t;
    }
    if (lane == 31) ws[w] = v;
    __syncthreads();
    if (w == 0) {
        int xv = ws[lane];
        #pragma unroll
        for (int o = 1; o < 32; o <<= 1) {
            int t = __shfl_up_sync(0xffffffffu, xv, o);
            if (lane >= o) xv += t;
        }
        ws[lane] = xv;
    }
    __syncthreads();
    int run = (v - sum) + (w > 0 ? ws[w - 1] : 0);
    for (int j = 0; j < PER; j++) {
        int idx = base + j;
        if (idx < NN) {
            int d = g_deg[idx];
            g_off[idx] = run; g_cur[idx] = run;
            run += d;
        }
    }
    if (tid == 0) g_off[NN] = ET;
}

__global__ void k_scatter(const int* __restrict__ ei) {
    int e = blockIdx.x * blockDim.x + threadIdx.x;
    if (e >= ET) return;
    int s, d;
    if (e < EE) { s = load_edge(ei, e); d = load_edge(ei, EE + e); }
    else        { s = d = e - EE; }
    if ((unsigned)d >= (unsigned)NN || (unsigned)s >= (unsigned)NN) return;
    int p = atomicAdd(&g_cur[d], 1);
    if ((unsigned)p < (unsigned)ET) g_srcid[p] = s;
}

// ---- GAT layer-1 aggregation over x (256B/edge), per-head softmax ----------
// out: g_ax[node][h*128 + c] = (sum_e w_e^h * x[src][c]) / den_h   (fp16)
__global__ void k_agg1x(void) {
    int node = (blockIdx.x * blockDim.x + threadIdx.x) >> 5;
    int lane = threadIdx.x & 31;
    if (node >= NN) return;
    int beg = g_off[node], end = g_off[node + 1];
    float4 adv = *(const float4*)&g_ad1[node * 4];
    int hsel = lane & 3;
    float adh = (hsel == 0) ? adv.x : (hsel == 1) ? adv.y : (hsel == 2) ? adv.z : adv.w;
    int c0 = lane * 4;   // halves

    float acc[4][4] = {};
    float den0 = 0.f, den1 = 0.f, den2 = 0.f, den3 = 0.f;
    int i = beg;
    for (; i + 2 <= end; i += 2) {
        int s0 = g_srcid[i], s1 = g_srcid[i + 1];
        float4 as0 = *(const float4*)&g_as1[s0 * 4];
        float4 as1v = *(const float4*)&g_as1[s1 * 4];
        uint2 v0 = *(const uint2*)&g_xh[(size_t)s0 * 128 + c0];
        uint2 v1 = *(const uint2*)&g_xh[(size_t)s1 * 128 + c0];
        float a0 = (hsel == 0) ? as0.x : (hsel == 1) ? as0.y : (hsel == 2) ? as0.z : as0.w;
        float a1 = (hsel == 0) ? as1v.x : (hsel == 1) ? as1v.y : (hsel == 2) ? as1v.z : as1v.w;
        float wl0 = __expf(lrelu(a0 + adh));
        float wl1 = __expf(lrelu(a1 + adh));
        float w00 = __shfl_sync(0xffffffffu, wl0, 0), w01 = __shfl_sync(0xffffffffu, wl0, 1);
        float w02 = __shfl_sync(0xffffffffu, wl0, 2), w03 = __shfl_sync(0xffffffffu, wl0, 3);
        float w10 = __shfl_sync(0xffffffffu, wl1, 0), w11 = __shfl_sync(0xffffffffu, wl1, 1);
        float w12 = __shfl_sync(0xffffffffu, wl1, 2), w13 = __shfl_sync(0xffffffffu, wl1, 3);
        den0 += w00 + w10; den1 += w01 + w11; den2 += w02 + w12; den3 += w03 + w13;
        float2 e0 = __half22float2(*(__half2*)&v0.x);
        float2 e1 = __half22float2(*(__half2*)&v0.y);
        float2 e2 = __half22float2(*(__half2*)&v1.x);
        float2 e3 = __half22float2(*(__half2*)&v1.y);
        float x00 = e0.x, x01 = e0.y, x02 = e1.x, x03 = e1.y;
        float x10 = e2.x, x11 = e2.y, x12 = e3.x, x13 = e3.y;
        acc[0][0] += w00 * x00 + w10 * x10; acc[0][1] += w00 * x01 + w10 * x11;
        acc[0][2] += w00 * x02 + w10 * x12; acc[0][3] += w00 * x03 + w10 * x13;
        acc[1][0] += w01 * x00 + w11 * x10; acc[1][1] += w01 * x01 + w11 * x11;
        acc[1][2] += w01 * x02 + w11 * x12; acc[1][3] += w01 * x03 + w11 * x13;
        acc[2][0] += w02 * x00 + w12 * x10; acc[2][1] += w02 * x01 + w12 * x11;
        acc[2][2] += w02 * x02 + w12 * x12; acc[2][3] += w02 * x03 + w12 * x13;
        acc[3][0] += w03 * x00 + w13 * x10; acc[3][1] += w03 * x01 + w13 * x11;
        acc[3][2] += w03 * x02 + w13 * x12; acc[3][3] += w03 * x03 + w13 * x13;
    }
    if (i < end) {
        int s = g_srcid[i];
        float4 as = *(const float4*)&g_as1[s * 4];
        uint2 v = *(const uint2*)&g_xh[(size_t)s * 128 + c0];
        float a = (hsel == 0) ? as.x : (hsel == 1) ? as.y : (hsel == 2) ? as.z : as.w;
        float wl = __expf(lrelu(a + adh));
        float w0 = __shfl_sync(0xffffffffu, wl, 0), w1 = __shfl_sync(0xffffffffu, wl, 1);
        float w2 = __shfl_sync(0xffffffffu, wl, 2), w3 = __shfl_sync(0xffffffffu, wl, 3);
        den0 += w0; den1 += w1; den2 += w2; den3 += w3;
        float2 e0 = __half22float2(*(__half2*)&v.x);
        float2 e1 = __half22float2(*(__half2*)&v.y);
        float xk[4] = {e0.x, e0.y, e1.x, e1.y};
        #pragma unroll
        for (int k = 0; k < 4; k++) {
            acc[0][k] += w0 * xk[k]; acc[1][k] += w1 * xk[k];
            acc[2][k] += w2 * xk[k]; acc[3][k] += w3 * xk[k];
        }
    }
    float inv[4];
    inv[0] = 1.f / (den0 + 1e-16f); inv[1] = 1.f / (den1 + 1e-16f);
    inv[2] = 1.f / (den2 + 1e-16f); inv[3] = 1.f / (den3 + 1e-16f);
    __half2* op = (__half2*)&g_ax[(size_t)node * 512];
    #pragma unroll
    for (int h = 0; h < 4; h++) {
        op[h * 64 + lane * 2]     = __floats2half2_rn(acc[h][0] * inv[h], acc[h][1] * inv[h]);
        op[h * 64 + lane * 2 + 1] = __floats2half2_rn(acc[h][2] * inv[h], acc[h][3] * inv[h]);
    }
}

// ---- head-sliced TC GEMM: g_hh[:,h*64:+64] = elu(aggx_h @ W1_h + b1_h) -----
// blockIdx.x = head, blockIdx.y = row tile. BM=128, N=64, K=128.
__global__ void k_hgemm_gat1(const float* __restrict__ b1) {
    __shared__ __half As[128][40];
    __shared__ __half Bs[64][42];
    int head = blockIdx.x;
    int bm = blockIdx.y * 128;
    int tid = threadIdx.x, lane = tid & 31, wid = tid >> 5;
    int wm = wid & 3, wn = wid >> 2;
    int g = lane >> 2, tc = lane & 3;
    float acc[2][4][4] = {};
    for (int k0 = 0; k0 < 128; k0 += 32) {
        #pragma unroll
        for (int t = 0; t < 2; t++) {
            int i = tid + t * 256;
            int r = i >> 2, seg = i & 3;
            int row = bm + r;
            uint4 v = make_uint4(0u, 0u, 0u, 0u);
            if (row < NN) v = *(const uint4*)&g_ax[(size_t)row * 512 + head * 128 + k0 + seg * 8];
            *(uint4*)&As[r][seg * 8] = v;
        }
        #pragma unroll
        for (int t = 0; t < 4; t++) {
            int i = tid + t * 256;
            int kk = i >> 5, nn = (i & 31) * 2;
            __half2 v = *(const __half2*)&g_w1h[(size_t)(k0 + kk) * 256 + head * 64 + nn];
            Bs[nn][kk]     = __low2half(v);
            Bs[nn + 1][kk] = __high2half(v);
        }
        __syncthreads();
        #pragma unroll
        for (int ks = 0; ks < 2; ks++) {
            int kb = ks * 16;
            uint32_t af[2][4], bf[4][2];
            #pragma unroll
            for (int mt = 0; mt < 2; mt++) {
                int r = wm * 32 + mt * 16 + g;
                af[mt][0] = *(const uint32_t*)&As[r][kb + tc * 2];
                af[mt][1] = *(const uint32_t*)&As[r + 8][kb + tc * 2];
                af[mt][2] = *(const uint32_t*)&As[r][kb + tc * 2 + 8];
                af[mt][3] = *(const uint32_t*)&As[r + 8][kb + tc * 2 + 8];
            }
            #pragma unroll
            for (int nt = 0; nt < 4; nt++) {
                int n = wn * 32 + nt * 8 + g;
                bf[nt][0] = *(const uint32_t*)&Bs[n][kb + tc * 2];
                bf[nt][1] = *(const uint32_t*)&Bs[n][kb + tc * 2 + 8];
            }
            #pragma unroll
            for (int mt = 0; mt < 2; mt++)
                #pragma unroll
                for (int nt = 0; nt < 4; nt++)
                    asm volatile(
                        "mma.sync.aligned.m16n8k16.row.col.f32.f16.f16.f32 "
                        "{%0,%1,%2,%3},{%4,%5,%6,%7},{%8,%9},{%0,%1,%2,%3};"
                        : "+f"(acc[mt][nt][0]), "+f"(acc[mt][nt][1]),
                          "+f"(acc[mt][nt][2]), "+f"(acc[mt][nt][3])
                        : "r"(af[mt][0]), "r"(af[mt][1]), "r"(af[mt][2]), "r"(af[mt][3]),
                          "r"(bf[nt][0]), "r"(bf[nt][1]));
        }
        __syncthreads();
    }
    #pragma unroll
    for (int mt = 0; mt < 2; mt++) {
        #pragma unroll
        for (int hf = 0; hf < 2; hf++) {
            int row = bm + wm * 32 + mt * 16 + g + hf * 8;
            if (row >= NN) continue;
            #pragma unroll
            for (int nt = 0; nt < 4; nt++) {
                int cl = wn * 32 + nt * 8 + tc * 2;
                float v0 = acc[mt][nt][hf * 2 + 0] + b1[head * 64 + cl];
                float v1 = acc[mt][nt][hf * 2 + 1] + b1[head * 64 + cl + 1];
                v0 = v0 > 0.f ? v0 : __expf(v0) - 1.f;
                v1 = v1 > 0.f ? v1 : __expf(v1) - 1.f;
                g_hh[(size_t)row * 128 + head * 32 + (cl >> 1)] = __floats2half2_rn(v0, v1);
            }
        }
    }
}

// ------- fp16 tensor-core GEMM + fused att epilogue (atomic-free) ----------
template<int K, int HS>
__global__ void k_hgemm_att(const __half* __restrict__ A, const __half* __restrict__ B,
                            __half2* __restrict__ Ch, int M, int N,
                            const float* __restrict__ att_s, const float* __restrict__ att_d,
                            float* __restrict__ as_out, float* __restrict__ ad_out) {
    __shared__ __half As[128][40];
    __shared__ __half Bs[64][42];
    __shared__ float sps[128][2];
    __shared__ float spd[128][2];
    int bm = blockIdx.y * 128, bn = blockIdx.x * 64;
    int tid = threadIdx.x, lane = tid & 31, wid = tid >> 5;
    int wm = wid & 3, wn = wid >> 2;
    int g = lane >> 2, tc = lane & 3;
    float acc[2][4][4] = {};
    for (int k0 = 0; k0 < K; k0 += 32) {
        #pragma unroll
        for (int t = 0; t < 2; t++) {
            int i = tid + t * 256;
            int r = i >> 2, seg = i & 3;
            int row = bm + r;
            uint4 v = make_uint4(0u, 0u, 0u, 0u);
            if (row < M) v = *(const uint4*)&A[(size_t)row * K + k0 + seg * 8];
            *(uint4*)&As[r][seg * 8] = v;
        }
        #pragma unroll
        for (int t = 0; t < 4; t++) {
            int i = tid + t * 256;
            int kk = i >> 5, nn = (i & 31) * 2;
            __half2 v = *(const __half2*)&B[(size_t)(k0 + kk) * N + bn + nn];
            Bs[nn][kk]     = __low2half(v);
            Bs[nn + 1][kk] = __high2half(v);
        }
        __syncthreads();
        #pragma unroll
        for (int ks = 0; ks < 2; ks++) {
            int kb = ks * 16;
            uint32_t af[2][4], bf[4][2];
            #pragma unroll
            for (int mt = 0; mt < 2; mt++) {
                int r = wm * 32 + mt * 16 + g;
                af[mt][0] = *(const uint32_t*)&As[r][kb + tc * 2];
                af[mt][1] = *(const uint32_t*)&As[r + 8][kb + tc * 2];
                af[mt][2] = *(const uint32_t*)&As[r][kb + tc * 2 + 8];
                af[mt][3] = *(const uint32_t*)&As[r + 8][kb + tc * 2 + 8];
            }
            #pragma unroll
            for (int nt = 0; nt < 4; nt++) {
                int n = wn * 32 + nt * 8 + g;
                bf[nt][0] = *(const uint32_t*)&Bs[n][kb + tc * 2];
                bf[nt][1] = *(const uint32_t*)&Bs[n][kb + tc * 2 + 8];
            }
            #pragma unroll
            for (int mt = 0; mt < 2; mt++)
                #pragma unroll
                for (int nt = 0; nt < 4; nt++)
                    asm volatile(
                        "mma.sync.aligned.m16n8k16.row.col.f32.f16.f16.f32 "
                        "{%0,%1,%2,%3},{%4,%5,%6,%7},{%8,%9},{%0,%1,%2,%3};"
                        : "+f"(acc[mt][nt][0]), "+f"(acc[mt][nt][1]),
                          "+f"(acc[mt][nt][2]), "+f"(acc[mt][nt][3])
                        : "r"(af[mt][0]), "r"(af[mt][1]), "r"(af[mt][2]), "r"(af[mt][3]),
                          "r"(bf[nt][0]), "r"(bf[nt][1]));
        }
        __syncthreads();
    }
    int hh = bn >> 6;
    int N2 = N >> 1;
    #pragma unroll
    for (int mt = 0; mt < 2; mt++) {
        #pragma unroll
        for (int hf = 0; hf < 2; hf++) {
            int rl = wm * 32 + mt * 16 + hf * 8 + g;
            int row = bm + rl;
            float ps = 0.f, pd = 0.f;
            if (row < M) {
                #pragma unroll
                for (int nt = 0; nt < 4; nt++) {
                    int cl = wn * 32 + nt * 8 + tc * 2;
                    float v0 = acc[mt][nt][hf * 2 + 0];
                    float v1 = acc[mt][nt][hf * 2 + 1];
                    Ch[(size_t)row * N2 + ((bn + cl) >> 1)] = __floats2half2_rn(v0, v1);
                    ps += v0 * att_s[bn + cl] + v1 * att_s[bn + cl + 1];
                    pd += v0 * att_d[bn + cl] + v1 * att_d[bn + cl + 1];
                }
            }
            ps += __shfl_xor_sync(0xffffffffu, ps, 1);
            pd += __shfl_xor_sync(0xffffffffu, pd, 1);
            ps += __shfl_xor_sync(0xffffffffu, ps, 2);
            pd += __shfl_xor_sync(0xffffffffu, pd, 2);
            if (tc == 0) { sps[rl][wn] = ps; spd[rl][wn] = pd; }
        }
    }
    __syncthreads();
    if (tid < 128) {
        int row = bm + tid;
        if (row < M) {
            as_out[row * HS + hh] = sps[tid][0] + sps[tid][1];
            ad_out[row * HS + hh] = spd[tid][0] + spd[tid][1];
        }
    }
}

// ------- fp16 tensor-core GEMM, bias(+ELU) epilogue, fp16 or fp32 out ------
template<int K, bool ELU, bool HALF_OUT>
__global__ void k_hgemm_epi(const __half* __restrict__ A, const __half* __restrict__ B,
                            __half2* __restrict__ Ch, float* __restrict__ Cf,
                            int M, int N, const float* __restrict__ bias) {
    __shared__ __half As[128][40];
    __shared__ __half Bs[64][42];
    int bm = blockIdx.y * 128, bn = blockIdx.x * 64;
    int tid = threadIdx.x, lane = tid & 31, wid = tid >> 5;
    int wm = wid & 3, wn = wid >> 2;
    int g = lane >> 2, tc = lane & 3;
    float acc[2][4][4] = {};
    for (int k0 = 0; k0 < K; k0 += 32) {
        #pragma unroll
        for (int t = 0; t < 2; t++) {
            int i = tid + t * 256;
            int r = i >> 2, seg = i & 3;
            int row = bm + r;
            uint4 v = make_uint4(0u, 0u, 0u, 0u);
            if (row < M) v = *(const uint4*)&A[(size_t)row * K + k0 + seg * 8];
            *(uint4*)&As[r][seg * 8] = v;
        }
        #pragma unroll
        for (int t = 0; t < 4; t++) {
            int i = tid + t * 256;
            int kk = i >> 5, nn = (i & 31) * 2;
            __half2 v = *(const __half2*)&B[(size_t)(k0 + kk) * N + bn + nn];
            Bs[nn][kk]     = __low2half(v);
            Bs[nn + 1][kk] = __high2half(v);
        }
        __syncthreads();
        #pragma unroll
        for (int ks = 0; ks < 2; ks++) {
            int kb = ks * 16;
            uint32_t af[2][4], bf[4][2];
            #pragma unroll
            for (int mt = 0; mt < 2; mt++) {
                int r = wm * 32 + mt * 16 + g;
                af[mt][0] = *(const uint32_t*)&As[r][kb + tc * 2];
                af[mt][1] = *(const uint32_t*)&As[r + 8][kb + tc * 2];
                af[mt][2] = *(const uint32_t*)&As[r][kb + tc * 2 + 8];
                af[mt][3] = *(const uint32_t*)&As[r + 8][kb + tc * 2 + 8];
            }
            #pragma unroll
            for (int nt = 0; nt < 4; nt++) {
                int n = wn * 32 + nt * 8 + g;
                bf[nt][0] = *(const uint32_t*)&Bs[n][kb + tc * 2];
                bf[nt][1] = *(const uint32_t*)&Bs[n][kb + tc * 2 + 8];
            }
            #pragma unroll
            for (int mt = 0; mt < 2; mt++)
                #pragma unroll
                for (int nt = 0; nt < 4; nt++)
                    asm volatile(
                        "mma.sync.aligned.m16n8k16.row.col.f32.f16.f16.f32 "
                        "{%0,%1,%2,%3},{%4,%5,%6,%7},{%8,%9},{%0,%1,%2,%3};"
                        : "+f"(acc[mt][nt][0]), "+f"(acc[mt][nt][1]),
                          "+f"(acc[mt][nt][2]), "+f"(acc[mt][nt][3])
                        : "r"(af[mt][0]), "r"(af[mt][1]), "r"(af[mt][2]), "r"(af[mt][3]),
                          "r"(bf[nt][0]), "r"(bf[nt][1]));
        }
        __syncthreads();
    }
    int N2 = N >> 1;
    #pragma unroll
    for (int mt = 0; mt < 2; mt++) {
        #pragma unroll
        for (int hf = 0; hf < 2; hf++) {
            int row = bm + wm * 32 + mt * 16 + g + hf * 8;
            if (row >= M) continue;
            #pragma unroll
            for (int nt = 0; nt < 4; nt++) {
                int cl = bn + wn * 32 + nt * 8 + tc * 2;
                float v0 = acc[mt][nt][hf * 2 + 0] + bias[cl];
                float v1 = acc[mt][nt][hf * 2 + 1] + bias[cl + 1];
                if (ELU) {
                    v0 = v0 > 0.f ? v0 : __expf(v0) - 1.f;
                    v1 = v1 > 0.f ? v1 : __expf(v1) - 1.f;
                }
                if (HALF_OUT)
                    Ch[(size_t)row * N2 + (cl >> 1)] = __floats2half2_rn(v0, v1);
                else
                    *(float2*)&Cf[(size_t)row * N + cl] = make_float2(v0, v1);
            }
        }
    }
}

// ---- fused GAT layer-2 agg + L2 normalize; writes fp32 z AND fp16 z -------
__global__ void k_agg2(const float* __restrict__ b2, float* __restrict__ zout) {
    int node = (blockIdx.x * blockDim.x + threadIdx.x) >> 5;
    int lane = threadIdx.x & 31;
    if (node >= NN) return;
    int beg = g_off[node], end = g_off[node + 1];
    float ad = g_ad2[node];

    float acc0 = 0.f, acc1 = 0.f, den = 0.f;
    int i = beg;
    for (; i + 2 <= end; i += 2) {
        int s0 = g_srcid[i], s1 = g_srcid[i + 1];
        float as0 = g_as2[s0], as1v = g_as2[s1];
        float2 h0 = __half22float2(g_h2h[(size_t)s0 * 32 + lane]);
        float2 h1 = __half22float2(g_h2h[(size_t)s1 * 32 + lane]);
        float w0 = __expf(lrelu(as0 + ad));
        float w1 = __expf(lrelu(as1v + ad));
        den += w0 + w1;
        acc0 += h0.x * w0 + h1.x * w1;
        acc1 += h0.y * w0 + h1.y * w1;
    }
    if (i < end) {
        int s = g_srcid[i];
        float w = __expf(lrelu(g_as2[s] + ad));
        den += w;
        float2 h = __half22float2(g_h2h[(size_t)s * 32 + lane]);
        acc0 += h.x * w; acc1 += h.y * w;
    }
    float inv = 1.f / (den + 1e-16f);
    float2 bb = *(const float2*)&b2[lane * 2];
    float z0 = acc0 * inv + bb.x;
    float z1 = acc1 * inv + bb.y;
    float ss = z0 * z0 + z1 * z1;
    #pragma unroll
    for (int o = 16; o > 0; o >>= 1)
        ss += __shfl_xor_sync(0xffffffffu, ss, o);
    float invn = 1.f / fmaxf(sqrtf(ss), 1e-12f);
    z0 *= invn; z1 *= invn;
    *(float2*)&zout[(size_t)node * 64 + lane * 2] = make_float2(z0, z1);
    g_zh[(size_t)node * 32 + lane] = __floats2half2_rn(z0, z1);
}

// ---------------- launcher ---------------------------------------------------
extern "C" void kernel_launch(void* const* d_in, const int* in_sizes, int n_in,
                              void* d_out, int out_size) {
    float* z = (float*)d_out;                       // [NN,64]
    float* xhat = (out_size >= 9600000) ? (z + (size_t)NN * 64) : 0;

    if (out_size != 9600000)
        k_zero_out<<<(out_size + 511) / 512, 512>>>((float*)d_out, out_size);

    // device addresses of scratch globals (host-passable)
    void *p_w2h, *p_dw1h, *p_dw2h, *p_hh, *p_h2h, *p_zh, *p_th;
    void *p_as2, *p_ad2;
    cudaGetSymbolAddress(&p_w2h,  g_w2h);
    cudaGetSymbolAddress(&p_dw1h, g_dw1h);
    cudaGetSymbolAddress(&p_dw2h, g_dw2h);
    cudaGetSymbolAddress(&p_hh,   g_hh);
    cudaGetSymbolAddress(&p_h2h,  g_h2h);
    cudaGetSymbolAddress(&p_zh,   g_zh);
    cudaGetSymbolAddress(&p_th,   g_th);
    cudaGetSymbolAddress(&p_as2,  g_as2);
    cudaGetSymbolAddress(&p_ad2,  g_ad2);

    // ---- input resolution: positional (dict order) verified by sizes ----
    static const int expect[14] = {6400000, 1600000, 32768, 256, 256, 256,
                                   16384, 64, 64, 64, 4096, 64, 8192, 128};
    bool positionalOK = (n_in == 14);
    if (positionalOK) {
        for (int i = 0; i < 14; i++) {
            int s = in_sizes[i];
            if (s != expect[i] && !(i == 1 && s == 3200000)) { positionalOK = false; break; }
        }
    }

    const float *x = 0, *W1 = 0, *W2 = 0, *dW1 = 0, *dW2 = 0, *db2 = 0;
    const float *atts1 = 0, *attd1 = 0, *b1 = 0, *atts2 = 0, *attd2 = 0, *b2 = 0, *db1 = 0;
    const int* ei = 0;

    if (positionalOK) {
        x     = (const float*)d_in[0];
        ei    = (const int*)  d_in[1];
        W1    = (const float*)d_in[2];
        atts1 = (const float*)d_in[3];
        attd1 = (const float*)d_in[4];
        b1    = (const float*)d_in[5];
        W2    = (const float*)d_in[6];
        atts2 = (const float*)d_in[7];
        attd2 = (const float*)d_in[8];
        b2    = (const float*)d_in[9];
        dW1   = (const float*)d_in[10];
        db1   = (const float*)d_in[11];
        dW2   = (const float*)d_in[12];
        db2   = (const float*)d_in[13];
    } else {
        const float* g256[3] = {0, 0, 0};
        const float* g64[4]  = {0, 0, 0, 0};
        int n256 = 0, n64 = 0;
        for (int i = 0; i < n_in; i++) {
            int s = in_sizes[i];
            const float* p = (const float*)d_in[i];
            if      (s == 6400000) x   = p;
            else if (s == 1600000 || s == 3200000) ei = (const int*)d_in[i];
            else if (s == 32768)   W1  = p;
            else if (s == 16384)   W2  = p;
            else if (s == 4096)    dW1 = p;
            else if (s == 8192)    dW2 = p;
            else if (s == 128)     db2 = p;
            else if (s == 256 && n256 < 3) g256[n256++] = p;
            else if (s == 64  && n64  < 4) g64[n64++]   = p;
        }
        bool dictLike = (n_in > 0 && in_sizes[0] == 6400000);
        atts1 = g256[dictLike ? 0 : 1];
        attd1 = g256[dictLike ? 1 : 0];
        b1    = g256[2];
        atts2 = g64[dictLike ? 0 : 1];
        attd2 = g64[dictLike ? 1 : 0];
        b2    = g64[2];
        db1   = g64[3];
        if (!x || !ei || !W1 || !W2 || !dW1 || !dW2 || !db2 || n256 < 3 || n64 < 4) {
            k_flag<<<1, 1>>>(z, 1e12f);
            return;
        }
    }

    // ---- single stream ----
    k_init   <<<(NN + 255) / 256, 256>>>(ei);
    k_count  <<<(ET + 255) / 256, 256>>>(ei);
    k_scan1  <<<1, 1024>>>();
    k_scatter<<<(ET + 255) / 256, 256>>>(ei);

    k_cvt<<<(CVT_TOTAL + 255) / 256, 256>>>(x, W1, W2, dW1, dW2);

    // ---- layer 1 (x-space aggregation) ----
    k_v<<<1, 512>>>(W1, atts1, attd1);
    k_attx<<<(NN * 32 + 255) / 256, 256>>>();
    k_agg1x<<<(NN * 32 + 255) / 256, 256>>>();
    {
        dim3 g(4, (NN + 127) / 128);
        k_hgemm_gat1<<<g, 256>>>(b1);
    }

    // ---- layer 2 ----
    {
        dim3 g(1, (NN + 127) / 128);
        k_hgemm_att<256, 1><<<g, 256>>>((const __half*)p_hh, (const __half*)p_w2h,
                                        (__half2*)p_h2h, NN, 64,
                                        atts2, attd2, (float*)p_as2, (float*)p_ad2);
    }
    k_agg2<<<(NN * 32 + 255) / 256, 256>>>(b2, z);

    // ---- decoder: two fp16 tensor-core GEMMs ----
    if (xhat) {
        dim3 g1(1, (NN + 127) / 128);
        k_hgemm_epi<64, true, true><<<g1, 256>>>(
            (const __half*)p_zh, (const __half*)p_dw1h,
            (__half2*)p_th, (float*)0, NN, 64, db1);
        dim3 g2(2, (NN + 127) / 128);
        k_hgemm_epi<64, false, false><<<g2, 256>>>(
            (const __half*)p_th, (const __half*)p_dw2h,
            (__half2*)0, xhat, NN, 128, db2);
    }
}

// round 17
// speedup vs baseline: 1.2652x; 1.2652x over previous
#include <cuda_runtime.h>
#include <cuda_fp16.h>
#include <cstdint>
#include <math.h>

#define NN 50000
#define EE 800000
#define ET (NN + EE)          // 850000 edges incl. self loops

// ---------------- scratch (device globals; no allocation allowed) ----------
__device__ __half  g_xh[(size_t)NN * 128];   // x in fp16
__device__ __half  g_w1h[128 * 256];         // W1 fp16
__device__ __half  g_w2h[256 * 64];          // W2 fp16
__device__ __half  g_dw1h[64 * 64];          // dW1 fp16
__device__ __half  g_dw2h[64 * 128];         // dW2 fp16
__device__ __half2 g_h1h[(size_t)NN * 128];  // h1 fp16 (gather + att src)
__device__ __half2 g_hh [(size_t)NN * 128];  // elu(gat1) fp16 (input to GEMM2)
__device__ __half2 g_h2h[(size_t)NN * 32];   // h2 fp16
__device__ __half2 g_zh [(size_t)NN * 32];   // z fp16 (decoder input)
__device__ __half2 g_th [(size_t)NN * 32];   // decoder hidden fp16
__device__ float g_as1[NN * 4];
__device__ float g_ad1[NN * 4];
__device__ float g_as2[NN];
__device__ float g_ad2[NN];
__device__ int   g_deg[NN];
__device__ int   g_off[NN + 1];
__device__ int   g_cur[NN];
__device__ int   g_srcid[ET];
__device__ int   g_ei64;

__device__ __forceinline__ float lrelu(float v) { return v >= 0.f ? v : 0.2f * v; }

__device__ __forceinline__ int load_edge(const int* __restrict__ ei, int j) {
    return g_ei64 ? ei[(size_t)j * 2] : ei[j];   // little-endian low word
}

__global__ void k_flag(float* __restrict__ z, float v) { z[0] = v; }

__global__ void k_zero_out(float* __restrict__ o, int n) {
    int i = blockIdx.x * blockDim.x + threadIdx.x;
    if (i < n) o[i] = 0.f;
}

// ------- init: zero degrees + dtype detect ----------------------------------
__global__ void k_init(const int* __restrict__ ei) {
    int i = blockIdx.x * blockDim.x + threadIdx.x;
    if (i < NN) g_deg[i] = 0;
    if (i == 0) {
        int odd_nz = 0, even_nz = 0;
        for (int j = 0; j < 256; j += 2) {
            if (ei[j]     != 0) even_nz++;
            if (ei[j + 1] != 0) odd_nz++;
        }
        g_ei64 = (odd_nz == 0 && even_nz > 0) ? 1 : 0;
    }
}

// ------- fp32 -> fp16 conversion of x, W1, W2, dW1, dW2 (pairwise) ----------
#define XPAIRS 3200000
#define W1PAIRS 16384
#define W2PAIRS 8192
#define DW1PAIRS 2048
#define DW2PAIRS 4096
#define CVT_TOTAL (XPAIRS + W1PAIRS + W2PAIRS + DW1PAIRS + DW2PAIRS)
__global__ void k_cvt(const float* __restrict__ x, const float* __restrict__ W1,
                      const float* __restrict__ W2, const float* __restrict__ dW1,
                      const float* __restrict__ dW2) {
    int p = blockIdx.x * blockDim.x + threadIdx.x;
    if (p < XPAIRS) {
        float2 v = *(const float2*)&x[(size_t)p * 2];
        *(__half2*)&g_xh[(size_t)p * 2] = __floats2half2_rn(v.x, v.y);
    } else if (p < XPAIRS + W1PAIRS) {
        int q = p - XPAIRS;
        float2 v = *(const float2*)&W1[(size_t)q * 2];
        *(__half2*)&g_w1h[(size_t)q * 2] = __floats2half2_rn(v.x, v.y);
    } else if (p < XPAIRS + W1PAIRS + W2PAIRS) {
        int q = p - XPAIRS - W1PAIRS;
        float2 v = *(const float2*)&W2[(size_t)q * 2];
        *(__half2*)&g_w2h[(size_t)q * 2] = __floats2half2_rn(v.x, v.y);
    } else if (p < XPAIRS + W1PAIRS + W2PAIRS + DW1PAIRS) {
        int q = p - XPAIRS - W1PAIRS - W2PAIRS;
        float2 v = *(const float2*)&dW1[(size_t)q * 2];
        *(__half2*)&g_dw1h[(size_t)q * 2] = __floats2half2_rn(v.x, v.y);
    } else if (p < CVT_TOTAL) {
        int q = p - XPAIRS - W1PAIRS - W2PAIRS - DW1PAIRS;
        float2 v = *(const float2*)&dW2[(size_t)q * 2];
        *(__half2*)&g_dw2h[(size_t)q * 2] = __floats2half2_rn(v.x, v.y);
    }
}

// ---------------- CSR build -------------------------------------------------
__global__ void k_count(const int* __restrict__ ei) {
    int e = blockIdx.x * blockDim.x + threadIdx.x;
    if (e >= ET) return;
    int dst = (e < EE) ? load_edge(ei, EE + e) : (e - EE);
    if ((unsigned)dst < (unsigned)NN) atomicAdd(&g_deg[dst], 1);
}

__global__ void k_scan1() {
    const int PER = 49;
    __shared__ int ws[32];
    int tid = threadIdx.x;
    int base = tid * PER;
    int sum = 0;
    for (int j = 0; j < PER; j++) { int idx = base + j; if (idx < NN) sum += g_deg[idx]; }
    int lane = tid & 31, w = tid >> 5;
    int v = sum;
    #pragma unroll
    for (int o = 1; o < 32; o <<= 1) {
        int t = __shfl_up_sync(0xffffffffu, v, o);
        if (lane >= o) v += t;
    }
    if (lane == 31) ws[w] = v;
    __syncthreads();
    if (w == 0) {
        int xv = ws[lane];
        #pragma unroll
        for (int o = 1; o < 32; o <<= 1) {
            int t = __shfl_up_sync(0xffffffffu, xv, o);
            if (lane >= o) xv += t;
        }
        ws[lane] = xv;
    }
    __syncthreads();
    int run = (v - sum) + (w > 0 ? ws[w - 1] : 0);
    for (int j = 0; j < PER; j++) {
        int idx = base + j;
        if (idx < NN) {
            int d = g_deg[idx];
            g_off[idx] = run; g_cur[idx] = run;
            run += d;
        }
    }
    if (tid == 0) g_off[NN] = ET;
}

__global__ void k_scatter(const int* __restrict__ ei) {
    int e = blockIdx.x * blockDim.x + threadIdx.x;
    if (e >= ET) return;
    int s, d;
    if (e < EE) { s = load_edge(ei, e); d = load_edge(ei, EE + e); }
    else        { s = d = e - EE; }
    if ((unsigned)d >= (unsigned)NN || (unsigned)s >= (unsigned)NN) return;
    int p = atomicAdd(&g_cur[d], 1);
    if ((unsigned)p < (unsigned)ET) g_srcid[p] = s;
}

// ------- fp16 tensor-core GEMM + fused att epilogue (atomic-free) ----------
template<int K, int HS>
__global__ void k_hgemm_att(const __half* __restrict__ A, const __half* __restrict__ B,
                            __half2* __restrict__ Ch, int M, int N,
                            const float* __restrict__ att_s, const float* __restrict__ att_d,
                            float* __restrict__ as_out, float* __restrict__ ad_out) {
    __shared__ __half As[128][40];
    __shared__ __half Bs[64][42];
    __shared__ float sps[128][2];
    __shared__ float spd[128][2];
    int bm = blockIdx.y * 128, bn = blockIdx.x * 64;
    int tid = threadIdx.x, lane = tid & 31, wid = tid >> 5;
    int wm = wid & 3, wn = wid >> 2;
    int g = lane >> 2, tc = lane & 3;
    float acc[2][4][4] = {};
    for (int k0 = 0; k0 < K; k0 += 32) {
        #pragma unroll
        for (int t = 0; t < 2; t++) {
            int i = tid + t * 256;
            int r = i >> 2, seg = i & 3;
            int row = bm + r;
            uint4 v = make_uint4(0u, 0u, 0u, 0u);
            if (row < M) v = *(const uint4*)&A[(size_t)row * K + k0 + seg * 8];
            *(uint4*)&As[r][seg * 8] = v;
        }
        #pragma unroll
        for (int t = 0; t < 4; t++) {
            int i = tid + t * 256;
            int kk = i >> 5, nn = (i & 31) * 2;
            __half2 v = *(const __half2*)&B[(size_t)(k0 + kk) * N + bn + nn];
            Bs[nn][kk]     = __low2half(v);
            Bs[nn + 1][kk] = __high2half(v);
        }
        __syncthreads();
        #pragma unroll
        for (int ks = 0; ks < 2; ks++) {
            int kb = ks * 16;
            uint32_t af[2][4], bf[4][2];
            #pragma unroll
            for (int mt = 0; mt < 2; mt++) {
                int r = wm * 32 + mt * 16 + g;
                af[mt][0] = *(const uint32_t*)&As[r][kb + tc * 2];
                af[mt][1] = *(const uint32_t*)&As[r + 8][kb + tc * 2];
                af[mt][2] = *(const uint32_t*)&As[r][kb + tc * 2 + 8];
                af[mt][3] = *(const uint32_t*)&As[r + 8][kb + tc * 2 + 8];
            }
            #pragma unroll
            for (int nt = 0; nt < 4; nt++) {
                int n = wn * 32 + nt * 8 + g;
                bf[nt][0] = *(const uint32_t*)&Bs[n][kb + tc * 2];
                bf[nt][1] = *(const uint32_t*)&Bs[n][kb + tc * 2 + 8];
            }
            #pragma unroll
            for (int mt = 0; mt < 2; mt++)
                #pragma unroll
                for (int nt = 0; nt < 4; nt++)
                    asm volatile(
                        "mma.sync.aligned.m16n8k16.row.col.f32.f16.f16.f32 "
                        "{%0,%1,%2,%3},{%4,%5,%6,%7},{%8,%9},{%0,%1,%2,%3};"
                        : "+f"(acc[mt][nt][0]), "+f"(acc[mt][nt][1]),
                          "+f"(acc[mt][nt][2]), "+f"(acc[mt][nt][3])
                        : "r"(af[mt][0]), "r"(af[mt][1]), "r"(af[mt][2]), "r"(af[mt][3]),
                          "r"(bf[nt][0]), "r"(bf[nt][1]));
        }
        __syncthreads();
    }
    int hh = bn >> 6;
    int N2 = N >> 1;
    #pragma unroll
    for (int mt = 0; mt < 2; mt++) {
        #pragma unroll
        for (int hf = 0; hf < 2; hf++) {
            int rl = wm * 32 + mt * 16 + hf * 8 + g;   // local row 0..127
            int row = bm + rl;
            float ps = 0.f, pd = 0.f;
            if (row < M) {
                #pragma unroll
                for (int nt = 0; nt < 4; nt++) {
                    int cl = wn * 32 + nt * 8 + tc * 2;
                    float v0 = acc[mt][nt][hf * 2 + 0];
                    float v1 = acc[mt][nt][hf * 2 + 1];
                    Ch[(size_t)row * N2 + ((bn + cl) >> 1)] = __floats2half2_rn(v0, v1);
                    ps += v0 * att_s[bn + cl] + v1 * att_s[bn + cl + 1];
                    pd += v0 * att_d[bn + cl] + v1 * att_d[bn + cl + 1];
                }
            }
            ps += __shfl_xor_sync(0xffffffffu, ps, 1);
            pd += __shfl_xor_sync(0xffffffffu, pd, 1);
            ps += __shfl_xor_sync(0xffffffffu, ps, 2);
            pd += __shfl_xor_sync(0xffffffffu, pd, 2);
            if (tc == 0) { sps[rl][wn] = ps; spd[rl][wn] = pd; }
        }
    }
    __syncthreads();
    if (tid < 128) {
        int row = bm + tid;
        if (row < M) {
            as_out[row * HS + hh] = sps[tid][0] + sps[tid][1];
            ad_out[row * HS + hh] = spd[tid][0] + spd[tid][1];
        }
    }
}

// ------- fp16 tensor-core GEMM, bias(+ELU) epilogue, fp16 or fp32 out ------
template<int K, bool ELU, bool HALF_OUT>
__global__ void k_hgemm_epi(const __half* __restrict__ A, const __half* __restrict__ B,
                            __half2* __restrict__ Ch, float* __restrict__ Cf,
                            int M, int N, const float* __restrict__ bias) {
    __shared__ __half As[128][40];
    __shared__ __half Bs[64][42];
    int bm = blockIdx.y * 128, bn = blockIdx.x * 64;
    int tid = threadIdx.x, lane = tid & 31, wid = tid >> 5;
    int wm = wid & 3, wn = wid >> 2;
    int g = lane >> 2, tc = lane & 3;
    float acc[2][4][4] = {};
    for (int k0 = 0; k0 < K; k0 += 32) {
        #pragma unroll
        for (int t = 0; t < 2; t++) {
            int i = tid + t * 256;
            int r = i >> 2, seg = i & 3;
            int row = bm + r;
            uint4 v = make_uint4(0u, 0u, 0u, 0u);
            if (row < M) v = *(const uint4*)&A[(size_t)row * K + k0 + seg * 8];
            *(uint4*)&As[r][seg * 8] = v;
        }
        #pragma unroll
        for (int t = 0; t < 4; t++) {
            int i = tid + t * 256;
            int kk = i >> 5, nn = (i & 31) * 2;
            __half2 v = *(const __half2*)&B[(size_t)(k0 + kk) * N + bn + nn];
            Bs[nn][kk]     = __low2half(v);
            Bs[nn + 1][kk] = __high2half(v);
        }
        __syncthreads();
        #pragma unroll
        for (int ks = 0; ks < 2; ks++) {
            int kb = ks * 16;
            uint32_t af[2][4], bf[4][2];
            #pragma unroll
            for (int mt = 0; mt < 2; mt++) {
                int r = wm * 32 + mt * 16 + g;
                af[mt][0] = *(const uint32_t*)&As[r][kb + tc * 2];
                af[mt][1] = *(const uint32_t*)&As[r + 8][kb + tc * 2];
                af[mt][2] = *(const uint32_t*)&As[r][kb + tc * 2 + 8];
                af[mt][3] = *(const uint32_t*)&As[r + 8][kb + tc * 2 + 8];
            }
            #pragma unroll
            for (int nt = 0; nt < 4; nt++) {
                int n = wn * 32 + nt * 8 + g;
                bf[nt][0] = *(const uint32_t*)&Bs[n][kb + tc * 2];
                bf[nt][1] = *(const uint32_t*)&Bs[n][kb + tc * 2 + 8];
            }
            #pragma unroll
            for (int mt = 0; mt < 2; mt++)
                #pragma unroll
                for (int nt = 0; nt < 4; nt++)
                    asm volatile(
                        "mma.sync.aligned.m16n8k16.row.col.f32.f16.f16.f32 "
                        "{%0,%1,%2,%3},{%4,%5,%6,%7},{%8,%9},{%0,%1,%2,%3};"
                        : "+f"(acc[mt][nt][0]), "+f"(acc[mt][nt][1]),
                          "+f"(acc[mt][nt][2]), "+f"(acc[mt][nt][3])
                        : "r"(af[mt][0]), "r"(af[mt][1]), "r"(af[mt][2]), "r"(af[mt][3]),
                          "r"(bf[nt][0]), "r"(bf[nt][1]));
        }
        __syncthreads();
    }
    int N2 = N >> 1;
    #pragma unroll
    for (int mt = 0; mt < 2; mt++) {
        #pragma unroll
        for (int hf = 0; hf < 2; hf++) {
            int row = bm + wm * 32 + mt * 16 + g + hf * 8;
            if (row >= M) continue;
            #pragma unroll
            for (int nt = 0; nt < 4; nt++) {
                int cl = bn + wn * 32 + nt * 8 + tc * 2;
                float v0 = acc[mt][nt][hf * 2 + 0] + bias[cl];
                float v1 = acc[mt][nt][hf * 2 + 1] + bias[cl + 1];
                if (ELU) {
                    v0 = v0 > 0.f ? v0 : __expf(v0) - 1.f;
                    v1 = v1 > 0.f ? v1 : __expf(v1) - 1.f;
                }
                if (HALF_OUT)
                    Ch[(size_t)row * N2 + (cl >> 1)] = __floats2half2_rn(v0, v1);
                else
                    *(float2*)&Cf[(size_t)row * N + cl] = make_float2(v0, v1);
            }
        }
    }
}

// ---- fused GAT layer-1 aggregation (warp/node, fp16 gather, unroll x2) ----
__global__ void k_agg1(const float* __restrict__ b1) {
    int node = (blockIdx.x * blockDim.x + threadIdx.x) >> 5;
    int lane = threadIdx.x & 31;
    if (node >= NN) return;
    int beg = g_off[node], end = g_off[node + 1];
    int hh = lane >> 3;
    float adh = g_ad1[node * 4 + hh];

    float a0=0,a1=0,a2=0,a3=0,a4=0,a5=0,a6=0,a7=0;
    float den = 0.f;
    int i = beg;
    for (; i + 2 <= end; i += 2) {
        int s0 = g_srcid[i], s1 = g_srcid[i + 1];
        float as0 = g_as1[s0 * 4 + hh], as1v = g_as1[s1 * 4 + hh];
        uint4 v0 = *(const uint4*)&g_h1h[(size_t)s0 * 128 + lane * 4];
        uint4 v1 = *(const uint4*)&g_h1h[(size_t)s1 * 128 + lane * 4];
        float w0 = __expf(lrelu(as0 + adh));
        float w1 = __expf(lrelu(as1v + adh));
        den += w0 + w1;
        float2 f;
        f = __half22float2(*(__half2*)&v0.x); a0 += f.x * w0; a1 += f.y * w0;
        f = __half22float2(*(__half2*)&v0.y); a2 += f.x * w0; a3 += f.y * w0;
        f = __half22float2(*(__half2*)&v0.z); a4 += f.x * w0; a5 += f.y * w0;
        f = __half22float2(*(__half2*)&v0.w); a6 += f.x * w0; a7 += f.y * w0;
        f = __half22float2(*(__half2*)&v1.x); a0 += f.x * w1; a1 += f.y * w1;
        f = __half22float2(*(__half2*)&v1.y); a2 += f.x * w1; a3 += f.y * w1;
        f = __half22float2(*(__half2*)&v1.z); a4 += f.x * w1; a5 += f.y * w1;
        f = __half22float2(*(__half2*)&v1.w); a6 += f.x * w1; a7 += f.y * w1;
    }
    if (i < end) {
        int s = g_srcid[i];
        float w = __expf(lrelu(g_as1[s * 4 + hh] + adh));
        den += w;
        uint4 v = *(const uint4*)&g_h1h[(size_t)s * 128 + lane * 4];
        float2 f;
        f = __half22float2(*(__half2*)&v.x); a0 += f.x * w; a1 += f.y * w;
        f = __half22float2(*(__half2*)&v.y); a2 += f.x * w; a3 += f.y * w;
        f = __half22float2(*(__half2*)&v.z); a4 += f.x * w; a5 += f.y * w;
        f = __half22float2(*(__half2*)&v.w); a6 += f.x * w; a7 += f.y * w;
    }
    float inv = 1.f / (den + 1e-16f);
    const float4* bp = (const float4*)&b1[lane * 8];
    float4 bb0 = bp[0], bb1 = bp[1];
    float o0 = a0*inv+bb0.x, o1 = a1*inv+bb0.y, o2 = a2*inv+bb0.z, o3 = a3*inv+bb0.w;
    float o4 = a4*inv+bb1.x, o5 = a5*inv+bb1.y, o6 = a6*inv+bb1.z, o7 = a7*inv+bb1.w;
    o0 = o0 > 0.f ? o0 : __expf(o0) - 1.f; o1 = o1 > 0.f ? o1 : __expf(o1) - 1.f;
    o2 = o2 > 0.f ? o2 : __expf(o2) - 1.f; o3 = o3 > 0.f ? o3 : __expf(o3) - 1.f;
    o4 = o4 > 0.f ? o4 : __expf(o4) - 1.f; o5 = o5 > 0.f ? o5 : __expf(o5) - 1.f;
    o6 = o6 > 0.f ? o6 : __expf(o6) - 1.f; o7 = o7 > 0.f ? o7 : __expf(o7) - 1.f;
    __half2* op = &g_hh[(size_t)node * 128 + lane * 4];
    op[0] = __floats2half2_rn(o0, o1);
    op[1] = __floats2half2_rn(o2, o3);
    op[2] = __floats2half2_rn(o4, o5);
    op[3] = __floats2half2_rn(o6, o7);
}

// ---- fused GAT layer-2 agg + L2 normalize; writes fp32 z AND fp16 z -------
__global__ void k_agg2(const float* __restrict__ b2, float* __restrict__ zout) {
    int node = (blockIdx.x * blockDim.x + threadIdx.x) >> 5;
    int lane = threadIdx.x & 31;
    if (node >= NN) return;
    int beg = g_off[node], end = g_off[node + 1];
    float ad = g_ad2[node];

    float acc0 = 0.f, acc1 = 0.f, den = 0.f;
    int i = beg;
    for (; i + 2 <= end; i += 2) {
        int s0 = g_srcid[i], s1 = g_srcid[i + 1];
        float as0 = g_as2[s0], as1v = g_as2[s1];
        float2 h0 = __half22float2(g_h2h[(size_t)s0 * 32 + lane]);
        float2 h1 = __half22float2(g_h2h[(size_t)s1 * 32 + lane]);
        float w0 = __expf(lrelu(as0 + ad));
        float w1 = __expf(lrelu(as1v + ad));
        den += w0 + w1;
        acc0 += h0.x * w0 + h1.x * w1;
        acc1 += h0.y * w0 + h1.y * w1;
    }
    if (i < end) {
        int s = g_srcid[i];
        float w = __expf(lrelu(g_as2[s] + ad));
        den += w;
        float2 h = __half22float2(g_h2h[(size_t)s * 32 + lane]);
        acc0 += h.x * w; acc1 += h.y * w;
    }
    float inv = 1.f / (den + 1e-16f);
    float2 bb = *(const float2*)&b2[lane * 2];
    float z0 = acc0 * inv + bb.x;
    float z1 = acc1 * inv + bb.y;
    float ss = z0 * z0 + z1 * z1;
    #pragma unroll
    for (int o = 16; o > 0; o >>= 1)
        ss += __shfl_xor_sync(0xffffffffu, ss, o);
    float invn = 1.f / fmaxf(sqrtf(ss), 1e-12f);
    z0 *= invn; z1 *= invn;
    *(float2*)&zout[(size_t)node * 64 + lane * 2] = make_float2(z0, z1);
    g_zh[(size_t)node * 32 + lane] = __floats2half2_rn(z0, z1);
}

// ---------------- launcher ---------------------------------------------------
extern "C" void kernel_launch(void* const* d_in, const int* in_sizes, int n_in,
                              void* d_out, int out_size) {
    float* z = (float*)d_out;                       // [NN,64]
    float* xhat = (out_size >= 9600000) ? (z + (size_t)NN * 64) : 0;

    if (out_size != 9600000)
        k_zero_out<<<(out_size + 511) / 512, 512>>>((float*)d_out, out_size);

    // device addresses of scratch globals (host-passable)
    void *p_xh, *p_w1h, *p_w2h, *p_dw1h, *p_dw2h, *p_h1h, *p_hh, *p_h2h, *p_zh, *p_th;
    void *p_as1, *p_ad1, *p_as2, *p_ad2;
    cudaGetSymbolAddress(&p_xh,   g_xh);
    cudaGetSymbolAddress(&p_w1h,  g_w1h);
    cudaGetSymbolAddress(&p_w2h,  g_w2h);
    cudaGetSymbolAddress(&p_dw1h, g_dw1h);
    cudaGetSymbolAddress(&p_dw2h, g_dw2h);
    cudaGetSymbolAddress(&p_h1h,  g_h1h);
    cudaGetSymbolAddress(&p_hh,   g_hh);
    cudaGetSymbolAddress(&p_h2h,  g_h2h);
    cudaGetSymbolAddress(&p_zh,   g_zh);
    cudaGetSymbolAddress(&p_th,   g_th);
    cudaGetSymbolAddress(&p_as1,  g_as1);
    cudaGetSymbolAddress(&p_ad1,  g_ad1);
    cudaGetSymbolAddress(&p_as2,  g_as2);
    cudaGetSymbolAddress(&p_ad2,  g_ad2);

    // ---- input resolution: positional (dict order) verified by sizes ----
    static const int expect[14] = {6400000, 1600000, 32768, 256, 256, 256,
                                   16384, 64, 64, 64, 4096, 64, 8192, 128};
    bool positionalOK = (n_in == 14);
    if (positionalOK) {
        for (int i = 0; i < 14; i++) {
            int s = in_sizes[i];
            if (s != expect[i] && !(i == 1 && s == 3200000)) { positionalOK = false; break; }
        }
    }

    const float *x = 0, *W1 = 0, *W2 = 0, *dW1 = 0, *dW2 = 0, *db2 = 0;
    const float *atts1 = 0, *attd1 = 0, *b1 = 0, *atts2 = 0, *attd2 = 0, *b2 = 0, *db1 = 0;
    const int* ei = 0;

    if (positionalOK) {
        x     = (const float*)d_in[0];
        ei    = (const int*)  d_in[1];
        W1    = (const float*)d_in[2];
        atts1 = (const float*)d_in[3];
        attd1 = (const float*)d_in[4];
        b1    = (const float*)d_in[5];
        W2    = (const float*)d_in[6];
        atts2 = (const float*)d_in[7];
        attd2 = (const float*)d_in[8];
        b2    = (const float*)d_in[9];
        dW1   = (const float*)d_in[10];
        db1   = (const float*)d_in[11];
        dW2   = (const float*)d_in[12];
        db2   = (const float*)d_in[13];
    } else {
        const float* g256[3] = {0, 0, 0};
        const float* g64[4]  = {0, 0, 0, 0};
        int n256 = 0, n64 = 0;
        for (int i = 0; i < n_in; i++) {
            int s = in_sizes[i];
            const float* p = (const float*)d_in[i];
            if      (s == 6400000) x   = p;
            else if (s == 1600000 || s == 3200000) ei = (const int*)d_in[i];
            else if (s == 32768)   W1  = p;
            else if (s == 16384)   W2  = p;
            else if (s == 4096)    dW1 = p;
            else if (s == 8192)    dW2 = p;
            else if (s == 128)     db2 = p;
            else if (s == 256 && n256 < 3) g256[n256++] = p;
            else if (s == 64  && n64  < 4) g64[n64++]   = p;
        }
        bool dictLike = (n_in > 0 && in_sizes[0] == 6400000);
        atts1 = g256[dictLike ? 0 : 1];
        attd1 = g256[dictLike ? 1 : 0];
        b1    = g256[2];
        atts2 = g64[dictLike ? 0 : 1];
        attd2 = g64[dictLike ? 1 : 0];
        b2    = g64[2];
        db1   = g64[3];
        if (!x || !ei || !W1 || !W2 || !dW1 || !dW2 || !db2 || n256 < 3 || n64 < 4) {
            k_flag<<<1, 1>>>(z, 1e12f);
            return;
        }
    }

    // ---- single stream (overlap regressed in R7/R14; x-space agg in R16) ----
    k_init   <<<(NN + 255) / 256, 256>>>(ei);
    k_count  <<<(ET + 255) / 256, 256>>>(ei);
    k_scan1  <<<1, 1024>>>();
    k_scatter<<<(ET + 255) / 256, 256>>>(ei);

    k_cvt<<<(CVT_TOTAL + 255) / 256, 256>>>(x, W1, W2, dW1, dW2);

    // ---- layer 1 ----
    {
        dim3 g(4, (NN + 127) / 128);
        k_hgemm_att<128, 4><<<g, 256>>>((const __half*)p_xh, (const __half*)p_w1h,
                                        (__half2*)p_h1h, NN, 256,
                                        atts1, attd1, (float*)p_as1, (float*)p_ad1);
    }
    k_agg1<<<(NN * 32 + 255) / 256, 256>>>(b1);

    // ---- layer 2 ----
    {
        dim3 g(1, (NN + 127) / 128);
        k_hgemm_att<256, 1><<<g, 256>>>((const __half*)p_hh, (const __half*)p_w2h,
                                        (__half2*)p_h2h, NN, 64,
                                        atts2, attd2, (float*)p_as2, (float*)p_ad2);
    }
    k_agg2<<<(NN * 32 + 255) / 256, 256>>>(b2, z);

    // ---- decoder: two fp16 tensor-core GEMMs ----
    if (xhat) {
        dim3 g1(1, (NN + 127) / 128);
        k_hgemm_epi<64, true, true><<<g1, 256>>>(
            (const __half*)p_zh, (const __half*)p_dw1h,
            (__half2*)p_th, (float*)0, NN, 64, db1);
        dim3 g2(2, (NN + 127) / 128);
        k_hgemm_epi<64, false, false><<<g2, 256>>>(
            (const __half*)p_th, (const __half*)p_dw2h,
            (__half2*)0, xhat, NN, 128, db2);
    }
}